// round 7
// baseline (speedup 1.0000x reference)
#include <cuda_runtime.h>
#include <cuda_fp16.h>
#include <cstdint>

// ===================== problem constants =====================
#define NTOK  16384          // B*N tokens
#define DIM   1024
#define EDIM  3072           // 3*DIM
#define BATCH 4
#define SEQ   4096
#define NSEG  32
#define SEGL  128            // SEQ / NSEG

// ===================== device scratch (no cudaMalloc allowed) ==========
__device__ __half g_ha[(size_t)NTOK * DIM];    // fp16 activations
__device__ __half g_wh[(size_t)EDIM * DIM];    // fp16 weights
__device__ float  g_qkva[(size_t)NTOK * EDIM]; // GEMM output [tok][3d]
__device__ float  g_carry[BATCH * NSEG * DIM]; // inclusive carries per segment
__device__ int    g_sflag[BATCH * NSEG * (DIM / 512)];

// ===================== PTX helpers (all valid on compute_103) ==========
__device__ __forceinline__ uint32_t smem_u32(const void* p) {
    uint32_t r;
    asm("{ .reg .u64 t; cvta.to.shared.u64 t, %1; cvt.u32.u64 %0, t; }" : "=r"(r) : "l"(p));
    return r;
}
__device__ __forceinline__ void cp16(uint32_t dst, const void* src) {
    asm volatile("cp.async.cg.shared.global [%0], [%1], 16;" :: "r"(dst), "l"(src));
}
#define CP_COMMIT() asm volatile("cp.async.commit_group;" ::: "memory")
#define CP_WAIT2()  asm volatile("cp.async.wait_group 2;" ::: "memory")

__device__ __forceinline__ void ldm_x4(uint32_t* r, uint32_t addr) {
    asm volatile("ldmatrix.sync.aligned.m8n8.x4.shared.b16 {%0,%1,%2,%3}, [%4];"
                 : "=r"(r[0]), "=r"(r[1]), "=r"(r[2]), "=r"(r[3]) : "r"(addr));
}
__device__ __forceinline__ void ldm_x2(uint32_t* r, uint32_t addr) {
    asm volatile("ldmatrix.sync.aligned.m8n8.x2.shared.b16 {%0,%1}, [%2];"
                 : "=r"(r[0]), "=r"(r[1]) : "r"(addr));
}
__device__ __forceinline__ void mma16816(float* c, const uint32_t* a, const uint32_t* b) {
    asm volatile(
        "mma.sync.aligned.m16n8k16.row.col.f32.f16.f16.f32 "
        "{%0,%1,%2,%3}, {%4,%5,%6,%7}, {%8,%9}, {%0,%1,%2,%3};"
        : "+f"(c[0]), "+f"(c[1]), "+f"(c[2]), "+f"(c[3])
        : "r"(a[0]), "r"(a[1]), "r"(a[2]), "r"(a[3]), "r"(b[0]), "r"(b[1]));
}

// ===================== kernel 0: clear lookback flags =====================
__global__ void clear_flags_kernel() {
    const int i = blockIdx.x * 128 + threadIdx.x;
    if (i < BATCH * NSEG * (DIM / 512)) g_sflag[i] = 0;
}

// ===================== kernel 1: RMSNorm -> fp16 activations ==============
__global__ void rmsnorm_kernel(const float* __restrict__ x, const float* __restrict__ gamma) {
    __shared__ float red[8];
    const int tok = blockIdx.x;
    const int tid = threadIdx.x;   // 256 threads, 4 elems each
    float4 v = ((const float4*)(x + (size_t)tok * DIM))[tid];
    float s = v.x * v.x + v.y * v.y + v.z * v.z + v.w * v.w;
    #pragma unroll
    for (int o = 16; o; o >>= 1) s += __shfl_xor_sync(0xffffffffu, s, o);
    if ((tid & 31) == 0) red[tid >> 5] = s;
    __syncthreads();
    if (tid == 0) {
        float t = 0.f;
        #pragma unroll
        for (int i = 0; i < 8; i++) t += red[i];
        red[0] = 32.0f / fmaxf(sqrtf(t), 1e-12f);   // sqrt(DIM)=32
    }
    __syncthreads();
    const float scl = red[0];
    float4 g = ((const float4*)gamma)[tid];
    __half2* hh = (__half2*)(g_ha + (size_t)tok * DIM);
    hh[2 * tid]     = __floats2half2_rn(v.x * scl * g.x, v.y * scl * g.y);
    hh[2 * tid + 1] = __floats2half2_rn(v.z * scl * g.z, v.w * scl * g.w);
}

// ===================== kernel 2: weight convert -> fp16 ====================
__global__ void wconv_kernel(const float* __restrict__ w) {
    size_t i4 = (size_t)blockIdx.x * 256 + threadIdx.x;   // EDIM*DIM/4 float4s
    float4 v = ((const float4*)w)[i4];
    ((__half2*)g_wh)[2 * i4]     = __floats2half2_rn(v.x, v.y);
    ((__half2*)g_wh)[2 * i4 + 1] = __floats2half2_rn(v.z, v.w);
}

// ===================== kernel 3: HMMA GEMM, CTA 128x256, warp tile 64x64 ===
// qkva[m][e] = sum_d h[m][d]*w[e][d]; BK=32, 4-stage cp.async ring.
// SMEM stage: A 128x32 fp16 (pitch 80B) + B 256x32 fp16 (pitch 80B).
#define PITCHB 80
#define A_TILE (128 * PITCHB)          // 10240
#define B_TILE (256 * PITCHB)          // 20480
#define OFF_A  0
#define OFF_B  A_TILE
#define STAGEB (A_TILE + B_TILE)       // 30720
#define NSTAGE 4
#define NKC    32                      // 1024 / 32
#define GEMM_SMEM (NSTAGE * STAGEB)    // 122880

__device__ __forceinline__ void load_stage(uint32_t sm_stage,
                                           const __half* A, const __half* B,
                                           int koff, int tid) {
    // A: 128 rows x 4 chunks = 512 cp16 (2/thread)
    #pragma unroll
    for (int i = 0; i < 2; i++) {
        const int c   = tid + i * 256;
        const int row = c >> 2;
        const int kc4 = c & 3;
        cp16(sm_stage + OFF_A + (uint32_t)(row * PITCHB + kc4 * 16),
             A + (size_t)row * DIM + koff + kc4 * 8);
    }
    // B: 256 rows x 4 chunks = 1024 cp16 (4/thread)
    #pragma unroll
    for (int i = 0; i < 4; i++) {
        const int c   = tid + i * 256;
        const int row = c >> 2;
        const int kc4 = c & 3;
        cp16(sm_stage + OFF_B + (uint32_t)(row * PITCHB + kc4 * 16),
             B + (size_t)row * DIM + koff + kc4 * 8);
    }
}

__global__ void __launch_bounds__(256, 1) gemm_kernel() {
    extern __shared__ char smem[];
    const uint32_t smem_base = smem_u32(smem);
    const int tid  = threadIdx.x;
    const int wid  = tid >> 5;
    const int lane = tid & 31;
    const int warp_m = wid >> 2;     // 0..1 -> 64-row strip
    const int warp_n = wid & 3;      // 0..3 -> 64-col strip
    const int ntile = blockIdx.x;    // 0..11 (fast dim -> A tile hot in L2)
    const int mtile = blockIdx.y;    // 0..127

    const __half* A = g_ha + (size_t)(mtile * 128) * DIM;
    const __half* B = g_wh + (size_t)(ntile * 256) * DIM;

    #pragma unroll
    for (int s = 0; s < NSTAGE - 1; s++) {
        load_stage(smem_base + s * STAGEB, A, B, s * 32, tid);
        CP_COMMIT();
    }

    float acc[4][8][4];
    #pragma unroll
    for (int mt = 0; mt < 4; mt++)
        #pragma unroll
        for (int nt = 0; nt < 8; nt++)
            #pragma unroll
            for (int r = 0; r < 4; r++) acc[mt][nt][r] = 0.f;

    const uint32_t a_base = (uint32_t)((warp_m * 64 + (lane & 15)) * PITCHB) + ((lane >> 4) << 4);
    const uint32_t b_base = (uint32_t)((warp_n * 64 + (lane & 7)) * PITCHB) + (((lane >> 3) & 1) << 4);

    for (int kc = 0; kc < NKC; kc++) {
        CP_WAIT2();                      // stage kc resident (<=2 groups pending)
        __syncthreads();
        if (kc + NSTAGE - 1 < NKC)
            load_stage(smem_base + ((kc + NSTAGE - 1) & (NSTAGE - 1)) * STAGEB,
                       A, B, (kc + NSTAGE - 1) * 32, tid);
        CP_COMMIT();

        const uint32_t sb = smem_base + (kc & (NSTAGE - 1)) * STAGEB;
        #pragma unroll
        for (int step = 0; step < 2; step++) {        // two K16 halves of BK=32
            uint32_t ah[4][4];
            #pragma unroll
            for (int mt = 0; mt < 4; mt++)
                ldm_x4(ah[mt], sb + OFF_A + a_base + step * 32 + mt * 16 * PITCHB);
            #pragma unroll
            for (int nt = 0; nt < 8; nt++) {
                uint32_t bf[2];
                ldm_x2(bf, sb + OFF_B + b_base + step * 32 + nt * 8 * PITCHB);
                #pragma unroll
                for (int mt = 0; mt < 4; mt++)
                    mma16816(acc[mt][nt], ah[mt], bf);
            }
        }
    }

    const int gid = lane >> 2, qid = lane & 3;
    #pragma unroll
    for (int mt = 0; mt < 4; mt++) {
        const int row0 = mtile * 128 + warp_m * 64 + mt * 16 + gid;
        #pragma unroll
        for (int nt = 0; nt < 8; nt++) {
            const int col = ntile * 256 + warp_n * 64 + nt * 8 + qid * 2;
            *(float2*)(g_qkva + (size_t)row0 * EDIM + col)       = make_float2(acc[mt][nt][0], acc[mt][nt][1]);
            *(float2*)(g_qkva + (size_t)(row0 + 8) * EDIM + col) = make_float2(acc[mt][nt][2], acc[mt][nt][3]);
        }
    }
}

// ===================== kernel 4: fused scan (chained carry, float4) =======
// grid (DIM/512, NSEG, BATCH), 128 threads, 4 channels/thread.
__global__ void __launch_bounds__(128) scan_fused_kernel(float* __restrict__ out) {
    const int tid = threadIdx.x;
    const int xc  = blockIdx.x;          // 0..1
    const int seg = blockIdx.y;          // 0..31
    const int b   = blockIdx.z;          // 0..3
    const int d0  = xc * 512 + tid * 4;
    const size_t tok0 = (size_t)b * SEQ + (size_t)seg * SEGL;

    const float* base_kv = g_qkva + tok0 * EDIM + DIM + d0;
    const float* base_av = g_qkva + tok0 * EDIM + 2 * DIM + d0;

    // ---- pass 1: segment-local scan ----
    float pa0 = 1.f, pa1 = 1.f, pa2 = 1.f, pa3 = 1.f;
    float y0 = 0.f, y1 = 0.f, y2 = 0.f, y3 = 0.f;
    #pragma unroll 4
    for (int i = 0; i < SEGL; i++) {
        const float4 kv = *(const float4*)(base_kv + (size_t)i * EDIM);
        const float4 av = *(const float4*)(base_av + (size_t)i * EDIM);
        const float a0 = 1.0f / (1.0f + __expf(-av.x));
        const float a1 = 1.0f / (1.0f + __expf(-av.y));
        const float a2 = 1.0f / (1.0f + __expf(-av.z));
        const float a3 = 1.0f / (1.0f + __expf(-av.w));
        y0 = a0 * y0 + kv.x;  pa0 *= a0;
        y1 = a1 * y1 + kv.y;  pa1 *= a1;
        y2 = a2 * y2 + kv.z;  pa2 *= a2;
        y3 = a3 * y3 + kv.w;  pa3 *= a3;
    }

    // ---- lookback: wait predecessor's inclusive carry, publish ours ----
    const int fstride = DIM / 512;                    // 2
    const int fidx = (b * NSEG + seg) * fstride + xc;
    float c0 = 0.f, c1 = 0.f, c2 = 0.f, c3 = 0.f;
    if (seg > 0) {
        const int* flagp = &g_sflag[fidx - fstride];
        if (tid == 0) {
            unsigned v;
            do {
                asm volatile("ld.acquire.gpu.global.b32 %0, [%1];" : "=r"(v) : "l"(flagp) : "memory");
            } while (v == 0);
        }
        __syncthreads();
        const float4 cp = *(const float4*)&g_carry[(size_t)(b * NSEG + seg - 1) * DIM + d0];
        c0 = cp.x; c1 = cp.y; c2 = cp.z; c3 = cp.w;
    }
    if (seg < NSEG - 1) {
        *(float4*)&g_carry[(size_t)(b * NSEG + seg) * DIM + d0] =
            make_float4(pa0 * c0 + y0, pa1 * c1 + y1, pa2 * c2 + y2, pa3 * c3 + y3);
        __threadfence();
        __syncthreads();
        if (tid == 0) {
            asm volatile("st.release.gpu.global.b32 [%0], %1;" :: "l"(&g_sflag[fidx]), "r"(1) : "memory");
        }
    }

    // ---- pass 2: recompute with carry-in, emit q*y ----
    const float* base_q = g_qkva + tok0 * EDIM + d0;
    float* outp = out + tok0 * DIM + d0;
    y0 = c0; y1 = c1; y2 = c2; y3 = c3;
    #pragma unroll 4
    for (int i = 0; i < SEGL; i++) {
        const float4 kv = *(const float4*)(base_kv + (size_t)i * EDIM);
        const float4 av = *(const float4*)(base_av + (size_t)i * EDIM);
        const float4 q  = *(const float4*)(base_q  + (size_t)i * EDIM);
        const float a0 = 1.0f / (1.0f + __expf(-av.x));
        const float a1 = 1.0f / (1.0f + __expf(-av.y));
        const float a2 = 1.0f / (1.0f + __expf(-av.z));
        const float a3 = 1.0f / (1.0f + __expf(-av.w));
        y0 = a0 * y0 + kv.x;
        y1 = a1 * y1 + kv.y;
        y2 = a2 * y2 + kv.z;
        y3 = a3 * y3 + kv.w;
        *(float4*)(outp + (size_t)i * DIM) = make_float4(q.x * y0, q.y * y1, q.z * y2, q.w * y3);
    }
}

// ===================== launcher =====================
extern "C" void kernel_launch(void* const* d_in, const int* in_sizes, int n_in,
                              void* d_out, int out_size) {
    const float* x     = (const float*)d_in[0];   // [4,4096,1024] f32
    const float* w     = (const float*)d_in[1];   // [3072,1024]  f32
    const float* gamma = (const float*)d_in[2];   // [1024]       f32
    float* out = (float*)d_out;

    cudaFuncSetAttribute(gemm_kernel, cudaFuncAttributeMaxDynamicSharedMemorySize, GEMM_SMEM);

    clear_flags_kernel<<<(BATCH * NSEG * (DIM / 512) + 127) / 128, 128>>>();
    rmsnorm_kernel<<<NTOK, 256>>>(x, gamma);
    wconv_kernel<<<(EDIM * DIM / 4) / 256, 256>>>(w);
    gemm_kernel<<<dim3(EDIM / 256, NTOK / 128), 256, GEMM_SMEM>>>();
    scan_fused_kernel<<<dim3(DIM / 512, NSEG, BATCH), 128>>>(out);
}

// round 8
// speedup vs baseline: 1.2726x; 1.2726x over previous
#include <cuda_runtime.h>
#include <cuda_fp16.h>
#include <cstdint>

// ===================== problem constants =====================
#define NTOK  16384          // B*N tokens
#define DIM   1024
#define EDIM  3072           // 3*DIM
#define BATCH 4
#define SEQ   4096
#define NSEG  32
#define SEGL  128            // SEQ / NSEG

// ===================== device scratch (no cudaMalloc allowed) ==========
__device__ __half g_ha[(size_t)NTOK * DIM];    // fp16 activations
__device__ __half g_wh[(size_t)EDIM * DIM];    // fp16 weights
__device__ float  g_qkva[(size_t)NTOK * EDIM]; // GEMM output [tok][3d]
__device__ float  g_carry[BATCH * NSEG * DIM]; // inclusive carries per segment
__device__ int    g_sflag[BATCH * NSEG * (DIM / 256)];

// ===================== PTX helpers (all valid on compute_103) ==========
__device__ __forceinline__ uint32_t smem_u32(const void* p) {
    uint32_t r;
    asm("{ .reg .u64 t; cvta.to.shared.u64 t, %1; cvt.u32.u64 %0, t; }" : "=r"(r) : "l"(p));
    return r;
}
__device__ __forceinline__ void cp16(uint32_t dst, const void* src) {
    asm volatile("cp.async.cg.shared.global [%0], [%1], 16;" :: "r"(dst), "l"(src));
}
#define CP_COMMIT() asm volatile("cp.async.commit_group;" ::: "memory")
#define CP_WAIT2()  asm volatile("cp.async.wait_group 2;" ::: "memory")

__device__ __forceinline__ void ldm_x4(uint32_t* r, uint32_t addr) {
    asm volatile("ldmatrix.sync.aligned.m8n8.x4.shared.b16 {%0,%1,%2,%3}, [%4];"
                 : "=r"(r[0]), "=r"(r[1]), "=r"(r[2]), "=r"(r[3]) : "r"(addr));
}
__device__ __forceinline__ void ldm_x2(uint32_t* r, uint32_t addr) {
    asm volatile("ldmatrix.sync.aligned.m8n8.x2.shared.b16 {%0,%1}, [%2];"
                 : "=r"(r[0]), "=r"(r[1]) : "r"(addr));
}
__device__ __forceinline__ void mma16816(float* c, const uint32_t* a, const uint32_t* b) {
    asm volatile(
        "mma.sync.aligned.m16n8k16.row.col.f32.f16.f16.f32 "
        "{%0,%1,%2,%3}, {%4,%5,%6,%7}, {%8,%9}, {%0,%1,%2,%3};"
        : "+f"(c[0]), "+f"(c[1]), "+f"(c[2]), "+f"(c[3])
        : "r"(a[0]), "r"(a[1]), "r"(a[2]), "r"(a[3]), "r"(b[0]), "r"(b[1]));
}

// ===================== kernel 0: clear lookback flags =====================
__global__ void clear_flags_kernel() {
    const int i = blockIdx.x * 128 + threadIdx.x;
    if (i < BATCH * NSEG * (DIM / 256)) g_sflag[i] = 0;
}

// ===================== kernel 1: RMSNorm -> fp16 activations ==============
__global__ void rmsnorm_kernel(const float* __restrict__ x, const float* __restrict__ gamma) {
    __shared__ float red[8];
    const int tok = blockIdx.x;
    const int tid = threadIdx.x;   // 256 threads, 4 elems each
    float4 v = ((const float4*)(x + (size_t)tok * DIM))[tid];
    float s = v.x * v.x + v.y * v.y + v.z * v.z + v.w * v.w;
    #pragma unroll
    for (int o = 16; o; o >>= 1) s += __shfl_xor_sync(0xffffffffu, s, o);
    if ((tid & 31) == 0) red[tid >> 5] = s;
    __syncthreads();
    if (tid == 0) {
        float t = 0.f;
        #pragma unroll
        for (int i = 0; i < 8; i++) t += red[i];
        red[0] = 32.0f / fmaxf(sqrtf(t), 1e-12f);   // sqrt(DIM)=32
    }
    __syncthreads();
    const float scl = red[0];
    float4 g = ((const float4*)gamma)[tid];
    __half2* hh = (__half2*)(g_ha + (size_t)tok * DIM);
    hh[2 * tid]     = __floats2half2_rn(v.x * scl * g.x, v.y * scl * g.y);
    hh[2 * tid + 1] = __floats2half2_rn(v.z * scl * g.z, v.w * scl * g.w);
}

// ===================== kernel 2: weight convert -> fp16 ====================
__global__ void wconv_kernel(const float* __restrict__ w) {
    size_t i4 = (size_t)blockIdx.x * 256 + threadIdx.x;   // EDIM*DIM/4 float4s
    float4 v = ((const float4*)w)[i4];
    ((__half2*)g_wh)[2 * i4]     = __floats2half2_rn(v.x, v.y);
    ((__half2*)g_wh)[2 * i4 + 1] = __floats2half2_rn(v.z, v.w);
}

// ===================== kernel 3: HMMA GEMM, CTA 128x128, 4 warps 64x64 =====
// qkva[m][e] = sum_d h[m][d]*w[e][d]; BK=32, 4-stage cp.async, 2 CTAs/SM.
// SMEM stage: A 128x32 fp16 + B 128x32 fp16, pitch 80 B.
#define PITCHB 80
#define TILEB  (128 * PITCHB)          // 10240
#define OFF_A  0
#define OFF_B  TILEB
#define STAGEB (2 * TILEB)             // 20480
#define NSTAGE 4
#define NKC    32                      // 1024 / 32
#define GEMM_SMEM (NSTAGE * STAGEB)    // 81920 -> 2 CTAs/SM

__device__ __forceinline__ void load_stage(uint32_t sm_stage,
                                           const __half* A, const __half* B,
                                           int koff, int tid) {
    // A + B: each 128 rows x 4 chunks of 16B = 512 cp16 -> 4/thread each
    #pragma unroll
    for (int i = 0; i < 4; i++) {
        const int c   = tid + i * 128;       // 0..511
        const int row = c >> 2;
        const int kc4 = c & 3;
        const uint32_t so = (uint32_t)(row * PITCHB + kc4 * 16);
        const size_t   go = (size_t)row * DIM + koff + kc4 * 8;
        cp16(sm_stage + OFF_A + so, A + go);
        cp16(sm_stage + OFF_B + so, B + go);
    }
}

__global__ void __launch_bounds__(128, 2) gemm_kernel() {
    extern __shared__ char smem[];
    const uint32_t smem_base = smem_u32(smem);
    const int tid  = threadIdx.x;
    const int wid  = tid >> 5;       // 0..3
    const int lane = tid & 31;
    const int warp_m = wid >> 1;     // 0..1 -> 64-row strip
    const int warp_n = wid & 1;      // 0..1 -> 64-col strip
    const int ntile = blockIdx.x;    // 0..23 (fast dim -> A tile hot in L2)
    const int mtile = blockIdx.y;    // 0..127

    const __half* A = g_ha + (size_t)(mtile * 128) * DIM;
    const __half* B = g_wh + (size_t)(ntile * 128) * DIM;

    #pragma unroll
    for (int s = 0; s < NSTAGE - 1; s++) {
        load_stage(smem_base + s * STAGEB, A, B, s * 32, tid);
        CP_COMMIT();
    }

    float acc[4][8][4];
    #pragma unroll
    for (int mt = 0; mt < 4; mt++)
        #pragma unroll
        for (int nt = 0; nt < 8; nt++)
            #pragma unroll
            for (int r = 0; r < 4; r++) acc[mt][nt][r] = 0.f;

    const uint32_t a_base = (uint32_t)((warp_m * 64 + (lane & 15)) * PITCHB) + ((lane >> 4) << 4);
    const uint32_t b_base = (uint32_t)((warp_n * 64 + (lane & 7)) * PITCHB) + (((lane >> 3) & 1) << 4);

    for (int kc = 0; kc < NKC; kc++) {
        CP_WAIT2();                      // stage kc resident (<=2 groups pending)
        __syncthreads();
        if (kc + NSTAGE - 1 < NKC)
            load_stage(smem_base + ((kc + NSTAGE - 1) & (NSTAGE - 1)) * STAGEB,
                       A, B, (kc + NSTAGE - 1) * 32, tid);
        CP_COMMIT();

        const uint32_t sb = smem_base + (kc & (NSTAGE - 1)) * STAGEB;
        #pragma unroll
        for (int step = 0; step < 2; step++) {        // two K16 halves of BK=32
            uint32_t ah[4][4];
            #pragma unroll
            for (int mt = 0; mt < 4; mt++)
                ldm_x4(ah[mt], sb + OFF_A + a_base + step * 32 + mt * 16 * PITCHB);
            #pragma unroll
            for (int nt = 0; nt < 8; nt++) {
                uint32_t bf[2];
                ldm_x2(bf, sb + OFF_B + b_base + step * 32 + nt * 8 * PITCHB);
                #pragma unroll
                for (int mt = 0; mt < 4; mt++)
                    mma16816(acc[mt][nt], ah[mt], bf);
            }
        }
    }

    const int gid = lane >> 2, qid = lane & 3;
    #pragma unroll
    for (int mt = 0; mt < 4; mt++) {
        const int row0 = mtile * 128 + warp_m * 64 + mt * 16 + gid;
        #pragma unroll
        for (int nt = 0; nt < 8; nt++) {
            const int col = ntile * 128 + warp_n * 64 + nt * 8 + qid * 2;
            *(float2*)(g_qkva + (size_t)row0 * EDIM + col)       = make_float2(acc[mt][nt][0], acc[mt][nt][1]);
            *(float2*)(g_qkva + (size_t)(row0 + 8) * EDIM + col) = make_float2(acc[mt][nt][2], acc[mt][nt][3]);
        }
    }
}

// ===================== kernel 4: fused scan (chained carry, 1 chan/thread) =
// grid (DIM/256, NSEG, BATCH) = 512 blocks x 256 threads -> ~27 warps/SM.
__global__ void __launch_bounds__(256) scan_fused_kernel(float* __restrict__ out) {
    const int tid = threadIdx.x;
    const int xc  = blockIdx.x;          // 0..3
    const int seg = blockIdx.y;          // 0..31
    const int b   = blockIdx.z;          // 0..3
    const int d   = xc * 256 + tid;
    const size_t tok0 = (size_t)b * SEQ + (size_t)seg * SEGL;

    const float* base_kv = g_qkva + tok0 * EDIM + DIM + d;
    const float* base_av = g_qkva + tok0 * EDIM + 2 * DIM + d;

    // ---- pass 1: segment-local scan ----
    float pa = 1.f, y = 0.f;
    #pragma unroll 8
    for (int i = 0; i < SEGL; i++) {
        const float kv = base_kv[(size_t)i * EDIM];
        const float av = base_av[(size_t)i * EDIM];
        const float a = 1.0f / (1.0f + __expf(-av));
        y = a * y + kv;
        pa *= a;
    }

    // ---- lookback: wait predecessor's inclusive carry, publish ours ----
    const int fstride = DIM / 256;                    // 4
    const int fidx = (b * NSEG + seg) * fstride + xc;
    float c = 0.f;
    if (seg > 0) {
        const int* flagp = &g_sflag[fidx - fstride];
        if (tid == 0) {
            unsigned v;
            do {
                asm volatile("ld.acquire.gpu.global.b32 %0, [%1];" : "=r"(v) : "l"(flagp) : "memory");
            } while (v == 0);
        }
        __syncthreads();
        c = g_carry[(size_t)(b * NSEG + seg - 1) * DIM + d];
    }
    if (seg < NSEG - 1) {
        g_carry[(size_t)(b * NSEG + seg) * DIM + d] = pa * c + y;
        __threadfence();
        __syncthreads();
        if (tid == 0) {
            asm volatile("st.release.gpu.global.b32 [%0], %1;" :: "l"(&g_sflag[fidx]), "r"(1) : "memory");
        }
    }

    // ---- pass 2: recompute with carry-in, emit q*y ----
    const float* base_q = g_qkva + tok0 * EDIM + d;
    float* outp = out + tok0 * DIM + d;
    y = c;
    #pragma unroll 8
    for (int i = 0; i < SEGL; i++) {
        const float kv = base_kv[(size_t)i * EDIM];
        const float av = base_av[(size_t)i * EDIM];
        const float q  = base_q [(size_t)i * EDIM];
        const float a = 1.0f / (1.0f + __expf(-av));
        y = a * y + kv;
        outp[(size_t)i * DIM] = q * y;
    }
}

// ===================== launcher =====================
extern "C" void kernel_launch(void* const* d_in, const int* in_sizes, int n_in,
                              void* d_out, int out_size) {
    const float* x     = (const float*)d_in[0];   // [4,4096,1024] f32
    const float* w     = (const float*)d_in[1];   // [3072,1024]  f32
    const float* gamma = (const float*)d_in[2];   // [1024]       f32
    float* out = (float*)d_out;

    cudaFuncSetAttribute(gemm_kernel, cudaFuncAttributeMaxDynamicSharedMemorySize, GEMM_SMEM);

    clear_flags_kernel<<<(BATCH * NSEG * (DIM / 256) + 127) / 128, 128>>>();
    rmsnorm_kernel<<<NTOK, 256>>>(x, gamma);
    wconv_kernel<<<(EDIM * DIM / 4) / 256, 256>>>(w);
    gemm_kernel<<<dim3(EDIM / 128, NTOK / 128), 128, GEMM_SMEM>>>();
    scan_fused_kernel<<<dim3(DIM / 256, NSEG, BATCH), 256>>>(out);
}

// round 10
// speedup vs baseline: 1.3760x; 1.0813x over previous
#include <cuda_runtime.h>
#include <cuda_fp16.h>
#include <cstdint>

// ===================== problem constants =====================
#define NTOK  16384          // B*N tokens
#define DIM   1024
#define EDIM  3072           // 3*DIM
#define BATCH 4
#define SEQ   4096
#define NSEG  32
#define SEGL  128            // SEQ / NSEG

// ===================== device scratch (no cudaMalloc allowed) ==========
__device__ __half g_ha[(size_t)NTOK * DIM];    // fp16 activations
__device__ __half g_wh[(size_t)EDIM * DIM];    // fp16 weights
__device__ float  g_qkva[(size_t)NTOK * EDIM]; // GEMM output [tok][3d]
__device__ float  g_sumA[BATCH * NSEG * DIM];  // per-segment gate products
__device__ float  g_sumY[BATCH * NSEG * DIM];  // per-segment local scan tails
__device__ float  g_carry[BATCH * NSEG * DIM]; // exclusive carry entering each segment

// ===================== PTX helpers (all valid on compute_103) ==========
__device__ __forceinline__ uint32_t smem_u32(const void* p) {
    uint32_t r;
    asm("{ .reg .u64 t; cvta.to.shared.u64 t, %1; cvt.u32.u64 %0, t; }" : "=r"(r) : "l"(p));
    return r;
}
__device__ __forceinline__ void cp16(uint32_t dst, const void* src) {
    asm volatile("cp.async.cg.shared.global [%0], [%1], 16;" :: "r"(dst), "l"(src));
}
#define CP_COMMIT() asm volatile("cp.async.commit_group;" ::: "memory")
#define CP_WAIT2()  asm volatile("cp.async.wait_group 2;" ::: "memory")

__device__ __forceinline__ void ldm_x4(uint32_t* r, uint32_t addr) {
    asm volatile("ldmatrix.sync.aligned.m8n8.x4.shared.b16 {%0,%1,%2,%3}, [%4];"
                 : "=r"(r[0]), "=r"(r[1]), "=r"(r[2]), "=r"(r[3]) : "r"(addr));
}
__device__ __forceinline__ void mma16816(float* c, const uint32_t* a, const uint32_t* b) {
    asm volatile(
        "mma.sync.aligned.m16n8k16.row.col.f32.f16.f16.f32 "
        "{%0,%1,%2,%3}, {%4,%5,%6,%7}, {%8,%9}, {%0,%1,%2,%3};"
        : "+f"(c[0]), "+f"(c[1]), "+f"(c[2]), "+f"(c[3])
        : "r"(a[0]), "r"(a[1]), "r"(a[2]), "r"(a[3]), "r"(b[0]), "r"(b[1]));
}

// ===================== kernel 1: RMSNorm -> fp16 activations ==============
__global__ void rmsnorm_kernel(const float* __restrict__ x, const float* __restrict__ gamma) {
    __shared__ float red[8];
    const int tok = blockIdx.x;
    const int tid = threadIdx.x;   // 256 threads, 4 elems each
    float4 v = ((const float4*)(x + (size_t)tok * DIM))[tid];
    float s = v.x * v.x + v.y * v.y + v.z * v.z + v.w * v.w;
    #pragma unroll
    for (int o = 16; o; o >>= 1) s += __shfl_xor_sync(0xffffffffu, s, o);
    if ((tid & 31) == 0) red[tid >> 5] = s;
    __syncthreads();
    if (tid == 0) {
        float t = 0.f;
        #pragma unroll
        for (int i = 0; i < 8; i++) t += red[i];
        red[0] = 32.0f / fmaxf(sqrtf(t), 1e-12f);   // sqrt(DIM)=32
    }
    __syncthreads();
    const float scl = red[0];
    float4 g = ((const float4*)gamma)[tid];
    __half2* hh = (__half2*)(g_ha + (size_t)tok * DIM);
    hh[2 * tid]     = __floats2half2_rn(v.x * scl * g.x, v.y * scl * g.y);
    hh[2 * tid + 1] = __floats2half2_rn(v.z * scl * g.z, v.w * scl * g.w);
}

// ===================== kernel 2: weight convert -> fp16 ====================
__global__ void wconv_kernel(const float* __restrict__ w) {
    size_t i4 = (size_t)blockIdx.x * 256 + threadIdx.x;   // EDIM*DIM/4 float4s
    float4 v = ((const float4*)w)[i4];
    ((__half2*)g_wh)[2 * i4]     = __floats2half2_rn(v.x, v.y);
    ((__half2*)g_wh)[2 * i4 + 1] = __floats2half2_rn(v.z, v.w);
}

// ===================== kernel 3: HMMA GEMM, CTA 128x128, 4 warps 64x64 =====
// qkva[m][e] = sum_d h[m][d]*w[e][d]; BK=32, 4-stage cp.async, 2 CTAs/SM,
// register-double-buffered fragments (LDSM for next step overlaps MMAs).
#define PITCHB 80
#define TILEB  (128 * PITCHB)          // 10240
#define OFF_A  0
#define OFF_B  TILEB
#define STAGEB (2 * TILEB)             // 20480
#define NSTAGE 4
#define NKC    32                      // 1024 / 32
#define GEMM_SMEM (NSTAGE * STAGEB)    // 81920 -> 2 CTAs/SM

__device__ __forceinline__ void load_stage(uint32_t sm_stage,
                                           const __half* A, const __half* B,
                                           int koff, int tid) {
    #pragma unroll
    for (int i = 0; i < 4; i++) {
        const int c   = tid + i * 128;       // 0..511
        const int row = c >> 2;
        const int kc4 = c & 3;
        const uint32_t so = (uint32_t)(row * PITCHB + kc4 * 16);
        const size_t   go = (size_t)row * DIM + koff + kc4 * 8;
        cp16(sm_stage + OFF_A + so, A + go);
        cp16(sm_stage + OFF_B + so, B + go);
    }
}

// Load one (stage, step) worth of fragments: A 4x ldm_x4, B 4x ldm_x4.
__device__ __forceinline__ void load_frags(uint32_t* ah, uint32_t* bf,
                                           uint32_t sb, uint32_t a_base, uint32_t b_base,
                                           int step) {
    #pragma unroll
    for (int mt = 0; mt < 4; mt++)
        ldm_x4(ah + 4 * mt, sb + OFF_A + a_base + step * 32 + mt * 16 * PITCHB);
    #pragma unroll
    for (int p = 0; p < 4; p++)
        ldm_x4(bf + 4 * p, sb + OFF_B + b_base + step * 32 + p * 16 * PITCHB);
}

__global__ void __launch_bounds__(128, 2) gemm_kernel() {
    extern __shared__ char smem[];
    const uint32_t smem_base = smem_u32(smem);
    const int tid  = threadIdx.x;
    const int wid  = tid >> 5;       // 0..3
    const int lane = tid & 31;
    const int warp_m = wid >> 1;     // 0..1 -> 64-row strip
    const int warp_n = wid & 1;      // 0..1 -> 64-col strip
    const int ntile = blockIdx.x;    // 0..23 (fast dim -> A tile hot in L2)
    const int mtile = blockIdx.y;    // 0..127

    const __half* A = g_ha + (size_t)(mtile * 128) * DIM;
    const __half* B = g_wh + (size_t)(ntile * 128) * DIM;

    #pragma unroll
    for (int s = 0; s < NSTAGE - 1; s++) {
        load_stage(smem_base + s * STAGEB, A, B, s * 32, tid);
        CP_COMMIT();
    }

    float acc[4][8][4];
    #pragma unroll
    for (int mt = 0; mt < 4; mt++)
        #pragma unroll
        for (int nt = 0; nt < 8; nt++)
            #pragma unroll
            for (int r = 0; r < 4; r++) acc[mt][nt][r] = 0.f;

    // fragment offsets
    const uint32_t a_base = (uint32_t)((warp_m * 64 + (lane & 15)) * PITCHB) + ((lane >> 4) << 4);
    // B x4 layout: regs 0,1 = rows n..n+7 (khalf lo/hi); regs 2,3 = rows n+8..n+15
    const uint32_t b_base = (uint32_t)((warp_n * 64 + ((lane >> 4) << 3) + (lane & 7)) * PITCHB)
                          + (((lane >> 3) & 1) << 4);

    uint32_t ah[2][16], bf[2][16];   // double-buffered per (kc,step)

    // prologue: stage 0 resident, preload frags (kc=0, step=0) into buf 0
    CP_WAIT2();
    __syncthreads();
    load_frags(ah[0], bf[0], smem_base, a_base, b_base, 0);

    for (int kc = 0; kc < NKC; kc++) {
        const uint32_t sb = smem_base + (kc & (NSTAGE - 1)) * STAGEB;
        // refill ring slot freed at kc-1 (stage kc+3)
        if (kc + NSTAGE - 1 < NKC)
            load_stage(smem_base + ((kc + NSTAGE - 1) & (NSTAGE - 1)) * STAGEB,
                       A, B, (kc + NSTAGE - 1) * 32, tid);
        CP_COMMIT();

        // prefetch (kc, step1) into buf1 (same stage: no barrier needed)
        load_frags(ah[1], bf[1], sb, a_base, b_base, 1);

        // MMAs for (kc, step0) — overlap the LDSM above
        #pragma unroll
        for (int nt = 0; nt < 8; nt++)
            #pragma unroll
            for (int mt = 0; mt < 4; mt++)
                mma16816(acc[mt][nt], &ah[0][4 * mt], &bf[0][2 * nt]);

        // stage barrier for kc+1, then prefetch (kc+1, step0) into buf0
        if (kc + 1 < NKC) {
            CP_WAIT2();                  // stage kc+1 resident
            __syncthreads();
            const uint32_t sbn = smem_base + ((kc + 1) & (NSTAGE - 1)) * STAGEB;
            load_frags(ah[0], bf[0], sbn, a_base, b_base, 0);
        }

        // MMAs for (kc, step1) — overlap the LDSM above
        #pragma unroll
        for (int nt = 0; nt < 8; nt++)
            #pragma unroll
            for (int mt = 0; mt < 4; mt++)
                mma16816(acc[mt][nt], &ah[1][4 * mt], &bf[1][2 * nt]);
    }

    const int gid = lane >> 2, qid = lane & 3;
    #pragma unroll
    for (int mt = 0; mt < 4; mt++) {
        const int row0 = mtile * 128 + warp_m * 64 + mt * 16 + gid;
        #pragma unroll
        for (int nt = 0; nt < 8; nt++) {
            const int col = ntile * 128 + warp_n * 64 + nt * 8 + qid * 2;
            *(float2*)(g_qkva + (size_t)row0 * EDIM + col)       = make_float2(acc[mt][nt][0], acc[mt][nt][1]);
            *(float2*)(g_qkva + (size_t)(row0 + 8) * EDIM + col) = make_float2(acc[mt][nt][2], acc[mt][nt][3]);
        }
    }
}

// ===================== kernel 4: scan pass A (local segment summaries) =====
__global__ void __launch_bounds__(256) scanA_kernel() {
    const int tid = threadIdx.x;
    const int d   = blockIdx.x * 256 + tid;   // 0..1023
    const int seg = blockIdx.y;
    const int b   = blockIdx.z;
    const size_t tok0 = (size_t)b * SEQ + (size_t)seg * SEGL;
    const float* base_kv = g_qkva + tok0 * EDIM + DIM + d;
    const float* base_av = g_qkva + tok0 * EDIM + 2 * DIM + d;
    float pa = 1.f, y = 0.f;
    #pragma unroll 8
    for (int i = 0; i < SEGL; i++) {
        const float kv = base_kv[(size_t)i * EDIM];
        const float av = base_av[(size_t)i * EDIM];
        const float a = 1.0f / (1.0f + __expf(-av));
        y = a * y + kv;
        pa *= a;
    }
    const size_t sidx = (size_t)(b * NSEG + seg) * DIM + d;
    g_sumA[sidx] = pa;
    g_sumY[sidx] = y;
}

// ===================== kernel 5: scan pass B (summary scan, tiny) ==========
__global__ void __launch_bounds__(256) scanB_kernel() {
    const int idx = blockIdx.x * 256 + threadIdx.x;   // 0..4095
    const int b = idx >> 10;
    const int d = idx & (DIM - 1);
    float c = 0.f;
    #pragma unroll
    for (int s = 0; s < NSEG; s++) {
        const size_t i = (size_t)(b * NSEG + s) * DIM + d;
        g_carry[i] = c;                       // exclusive carry entering segment s
        c = g_sumA[i] * c + g_sumY[i];
    }
}

// ===================== kernel 6: scan pass C (recompute + q*y) =============
__global__ void __launch_bounds__(256) scanC_kernel(float* __restrict__ out) {
    const int tid = threadIdx.x;
    const int d   = blockIdx.x * 256 + tid;
    const int seg = blockIdx.y;
    const int b   = blockIdx.z;
    const size_t tok0 = (size_t)b * SEQ + (size_t)seg * SEGL;
    const float* base_q  = g_qkva + tok0 * EDIM + d;
    const float* base_kv = g_qkva + tok0 * EDIM + DIM + d;
    const float* base_av = g_qkva + tok0 * EDIM + 2 * DIM + d;
    float* outp = out + tok0 * DIM + d;
    float y = g_carry[(size_t)(b * NSEG + seg) * DIM + d];
    #pragma unroll 8
    for (int i = 0; i < SEGL; i++) {
        const float kv = base_kv[(size_t)i * EDIM];
        const float av = base_av[(size_t)i * EDIM];
        const float q  = base_q [(size_t)i * EDIM];
        const float a = 1.0f / (1.0f + __expf(-av));
        y = a * y + kv;
        outp[(size_t)i * DIM] = q * y;
    }
}

// ===================== launcher =====================
extern "C" void kernel_launch(void* const* d_in, const int* in_sizes, int n_in,
                              void* d_out, int out_size) {
    const float* x     = (const float*)d_in[0];   // [4,4096,1024] f32
    const float* w     = (const float*)d_in[1];   // [3072,1024]  f32
    const float* gamma = (const float*)d_in[2];   // [1024]       f32
    float* out = (float*)d_out;

    cudaFuncSetAttribute(gemm_kernel, cudaFuncAttributeMaxDynamicSharedMemorySize, GEMM_SMEM);

    rmsnorm_kernel<<<NTOK, 256>>>(x, gamma);
    wconv_kernel<<<(EDIM * DIM / 4) / 256, 256>>>(w);
    gemm_kernel<<<dim3(EDIM / 128, NTOK / 128), 128, GEMM_SMEM>>>();
    scanA_kernel<<<dim3(DIM / 256, NSEG, BATCH), 256>>>();
    scanB_kernel<<<BATCH * DIM / 256, 256>>>();
    scanC_kernel<<<dim3(DIM / 256, NSEG, BATCH), 256>>>(out);
}